// round 4
// baseline (speedup 1.0000x reference)
#include <cuda_runtime.h>
#include <math.h>

// Shapes (fixed by the problem)
#define BB 128
#define NN 500
#define CC 80
// Head index used = 5 (last of 6)

// d_out layout (float32, 320000 elems):
//   [0      : 128000) boxes_next (B,N,2)
//   [128000 : 192000) scores     (B,N)
//   [192000 : 256000) labels     (B,N) as float
//   [256000 : 320000) nms_keep   (B,N) as 0/1 float
#define OFF_SCORES 128000
#define OFF_LABELS 192000
#define OFF_KEEP   256000

__device__ int g_keep[512];  // keep mask computed from batch 0 (n < 500)

// ---------------------------------------------------------------------------
// Kernel A: one warp per (b,n) row of predicted_class[5].
// Computes softmax score (max over first 79 classes), argmax label,
// and for b==0 the keep mask (max logit over all 80 > 0  <=>  sigmoid > 0.5).
// Fully coalesced: each warp reads 320 contiguous bytes.
// ---------------------------------------------------------------------------
__global__ __launch_bounds__(256)
void scores_kernel(const float* __restrict__ pc, float* __restrict__ out)
{
    int warp_id = (blockIdx.x * blockDim.x + threadIdx.x) >> 5;
    int lane    = threadIdx.x & 31;
    if (warp_id >= BB * NN) return;

    const float* row = pc + (size_t)5 * BB * NN * CC + (size_t)warp_id * CC;

    float x0 = row[lane];
    float x1 = row[lane + 32];
    float x2 = (lane < 16) ? row[lane + 64] : -INFINITY;

    // max over all 80 (for softmax normalization AND the keep mask)
    float m = fmaxf(fmaxf(x0, x1), x2);
    #pragma unroll
    for (int o = 16; o; o >>= 1) m = fmaxf(m, __shfl_xor_sync(0xffffffffu, m, o));

    // sum exp over all 80
    float s = __expf(x0 - m) + __expf(x1 - m) + ((lane < 16) ? __expf(x2 - m) : 0.0f);
    #pragma unroll
    for (int o = 16; o; o >>= 1) s += __shfl_xor_sync(0xffffffffu, s, o);

    // argmax over first 79 classes (exclude index 79 = chunk2 lane 15).
    // Ties resolve to the smallest index (jnp.argmax semantics).
    float v  = x0;
    int   ai = lane;
    if (x1 > v)               { v = x1; ai = lane + 32; }
    if (lane < 15 && x2 > v)  { v = x2; ai = lane + 64; }
    #pragma unroll
    for (int o = 16; o; o >>= 1) {
        float ov = __shfl_xor_sync(0xffffffffu, v, o);
        int   oi = __shfl_xor_sync(0xffffffffu, ai, o);
        if (ov > v || (ov == v && oi < ai)) { v = ov; ai = oi; }
    }

    if (lane == 0) {
        out[OFF_SCORES + warp_id] = __expf(v - m) / s;   // softmax prob of argmax
        out[OFF_LABELS + warp_id] = (float)ai;
        if (warp_id < NN) g_keep[warp_id] = (m > 0.0f);  // batch 0 rows are ids 0..499
    }
}

// ---------------------------------------------------------------------------
// Kernel C: one block per batch.
//  - Fused DDIM box update (needs g_keep from kernel A)
//  - Label-bucketed 1-D NMS: counting sort by label, then per-label
//    insertion sort by (score desc, idx asc) + greedy suppression.
//    Cross-label pairs never interact (same-label gate), so per-label
//    greedy in global score order == reference's global greedy.
// ---------------------------------------------------------------------------
__global__ __launch_bounds__(256)
void nms_boxes_kernel(const float* __restrict__ boxes_t,
                      const float* __restrict__ pb,
                      const float* __restrict__ noise,
                      const float* __restrict__ fresh,
                      const float* __restrict__ ac,
                      const int*   __restrict__ t_now_p,
                      const int*   __restrict__ t_next_p,
                      float* __restrict__ out)
{
    const int b   = blockIdx.x;
    const int tid = threadIdx.x;

    __shared__ float sx1[NN], sx2[NN], sw[NN];
    __shared__ unsigned long long skey[NN];
    __shared__ int   slab[NN];
    __shared__ int   hist[CC], offs[CC], cur[CC];
    __shared__ short grouped[NN];
    __shared__ char  sup[NN];

    if (tid < CC) hist[tid] = 0;
    __syncthreads();

    // DDIM scalars (identical fp32 op sequence to the reference)
    const int   t_now      = *t_now_p;
    const int   t_next     = *t_next_p;
    const float alpha      = ac[t_now];
    const float alpha_next = ac[t_next];
    const float sqrt_recip   = sqrtf(1.0f / alpha);
    const float sqrt_recipm1 = sqrtf(1.0f / alpha - 1.0f);
    const float sigma = sqrtf((1.0f - alpha / alpha_next) * (1.0f - alpha_next)
                              / (1.0f - alpha));
    const float ccoef = sqrtf(1.0f - alpha_next - sigma * sigma);
    const float sq_an = sqrtf(alpha_next);

    const float* pb5 = pb + (size_t)5 * BB * NN * 2;

    for (int n = tid; n < NN; n += blockDim.x) {
        size_t base = ((size_t)b * NN + n) * 2;
        float c0 = pb5[base];       // boxes_start center
        float w0 = pb5[base + 1];   // boxes_start width (raw)

        // --- box update (both coords) ---
        int   kp = g_keep[n];
        float bs0 = c0, bs1 = w0;
        {
            float pn0 = (sqrt_recip * boxes_t[base]     - bs0) / sqrt_recipm1;
            float pn1 = (sqrt_recip * boxes_t[base + 1] - bs1) / sqrt_recipm1;
            float u0  = bs0 * sq_an + ccoef * pn0 + sigma * noise[base];
            float u1  = bs1 * sq_an + ccoef * pn1 + sigma * noise[base + 1];
            out[base]     = kp ? u0 : fresh[base];
            out[base + 1] = kp ? u1 : fresh[base + 1];
        }

        // --- NMS staging ---
        float w = fmaxf(w0, 0.0001f);
        sx1[n] = c0 - w * 0.5f;
        sx2[n] = c0 + w * 0.5f;
        sw[n]  = w;

        float sc = out[OFF_SCORES + b * NN + n];
        unsigned u = __float_as_uint(sc);                 // scores > 0 always
        skey[n] = ((unsigned long long)(~u) << 32) | (unsigned)n;  // asc == (score desc, idx asc)
        int lab = (int)out[OFF_LABELS + b * NN + n];
        slab[n] = lab;
        sup[n]  = 0;
        atomicAdd(&hist[lab], 1);
    }
    __syncthreads();

    if (tid == 0) {
        int acc = 0;
        for (int l = 0; l < CC; ++l) { offs[l] = acc; cur[l] = acc; acc += hist[l]; }
    }
    __syncthreads();

    for (int n = tid; n < NN; n += blockDim.x) {
        int pos = atomicAdd(&cur[slab[n]], 1);
        grouped[pos] = (short)n;
    }
    __syncthreads();

    if (tid < CC) {
        int k = hist[tid], base0 = offs[tid];
        // insertion sort the group by key ascending (score desc, idx asc)
        for (int a = 1; a < k; ++a) {
            short gi = grouped[base0 + a];
            unsigned long long kv = skey[gi];
            int p = a - 1;
            while (p >= 0 && skey[grouped[base0 + p]] > kv) {
                grouped[base0 + p + 1] = grouped[base0 + p];
                --p;
            }
            grouped[base0 + p + 1] = gi;
        }
        // greedy suppression within the group
        for (int a = 0; a < k; ++a) {
            int i = grouped[base0 + a];
            if (sup[i]) continue;
            float x1i = sx1[i], x2i = sx2[i], wi = sw[i];
            for (int q = a + 1; q < k; ++q) {
                int j = grouped[base0 + q];
                float inter = fminf(x2i, sx2[j]) - fmaxf(x1i, sx1[j]);
                inter = fmaxf(0.0f, inter);
                float uni = wi + sw[j] - inter;
                if (inter / fmaxf(uni, 1e-9f) > 0.5f) sup[j] = 1;
            }
        }
    }
    __syncthreads();

    for (int n = tid; n < NN; n += blockDim.x)
        out[OFF_KEEP + b * NN + n] = sup[n] ? 0.0f : 1.0f;
}

// ---------------------------------------------------------------------------
// Inputs (metadata order):
//  0 boxes_t          (128,500,2)   f32
//  1 predicted_class  (6,128,500,80) f32
//  2 predicted_boxes  (6,128,500,2) f32
//  3 noise            (128,500,2)   f32
//  4 fresh_noise      (128,500,2)   f32
//  5 alphas_cumprod   (1000,)       f32
//  6 t_now            scalar        i32
//  7 t_next           scalar        i32
// ---------------------------------------------------------------------------
extern "C" void kernel_launch(void* const* d_in, const int* in_sizes, int n_in,
                              void* d_out, int out_size)
{
    const float* boxes_t = (const float*)d_in[0];
    const float* pc      = (const float*)d_in[1];
    const float* pb      = (const float*)d_in[2];
    const float* noise   = (const float*)d_in[3];
    const float* fresh   = (const float*)d_in[4];
    const float* ac      = (const float*)d_in[5];
    const int*   t_now   = (const int*)d_in[6];
    const int*   t_next  = (const int*)d_in[7];
    float* out = (float*)d_out;

    // Kernel A: 64000 rows, 1 warp each -> 8000 blocks of 256 threads
    int rows = BB * NN;
    int blocksA = (rows * 32 + 255) / 256;
    scores_kernel<<<blocksA, 256>>>(pc, out);

    // Kernel C: one block per batch (reads g_keep + scores/labels written by A)
    nms_boxes_kernel<<<BB, 256>>>(boxes_t, pb, noise, fresh, ac, t_now, t_next, out);
}

// round 5
// speedup vs baseline: 2.0116x; 2.0116x over previous
#include <cuda_runtime.h>
#include <math.h>

// Shapes (fixed by the problem)
#define BB 128
#define NN 500
#define CC 80
// Head index used = 5 (last of 6)

// d_out layout (float32, 320000 elems):
//   [0      : 128000) boxes_next (B,N,2)
//   [128000 : 192000) scores     (B,N)
//   [192000 : 256000) labels     (B,N) as float
//   [256000 : 320000) nms_keep   (B,N) as 0/1 float
#define OFF_SCORES 128000
#define OFF_LABELS 192000
#define OFF_KEEP   256000

#define NEG_BIG (-3.0e38f)

__device__ int g_keep[512];  // keep mask computed from batch 0 (n < 500)

// ---------------------------------------------------------------------------
// Kernel A: one warp per (b,n) row of predicted_class[5].
// float4 loads: lanes 0..19 each read 16 B (whole row = 320 B contiguous).
// Computes softmax score (max prob over first 79 classes), argmax label,
// and for b==0 the keep mask (max logit over all 80 > 0  <=>  sigmoid > 0.5).
// ---------------------------------------------------------------------------
__global__ __launch_bounds__(256)
void scores_kernel(const float* __restrict__ pc, float* __restrict__ out)
{
    int warp_id = (blockIdx.x * blockDim.x + threadIdx.x) >> 5;
    int lane    = threadIdx.x & 31;
    if (warp_id >= BB * NN) return;

    const float4* row = (const float4*)(pc + (size_t)5 * BB * NN * CC
                                           + (size_t)warp_id * CC);
    float4 x;
    if (lane < 20) x = __ldg(row + lane);
    else           x = make_float4(NEG_BIG, NEG_BIG, NEG_BIG, NEG_BIG);

    // max over all 80 (softmax normalization AND keep mask)
    float m = fmaxf(fmaxf(x.x, x.y), fmaxf(x.z, x.w));
    #pragma unroll
    for (int o = 16; o; o >>= 1) m = fmaxf(m, __shfl_xor_sync(0xffffffffu, m, o));

    // sum exp over all 80
    float s = 0.0f;
    if (lane < 20)
        s = __expf(x.x - m) + __expf(x.y - m) + __expf(x.z - m) + __expf(x.w - m);
    #pragma unroll
    for (int o = 16; o; o >>= 1) s += __shfl_xor_sync(0xffffffffu, s, o);

    // argmax over first 79 classes (exclude idx 79 = lane 19 .w).
    // Ties resolve to the smallest index (jnp.argmax semantics): strict >.
    float v  = NEG_BIG;
    int   ai = 0x7fffffff;
    if (lane < 20) {
        int b0 = lane * 4;
        v = x.x; ai = b0;
        if (x.y > v) { v = x.y; ai = b0 + 1; }
        if (x.z > v) { v = x.z; ai = b0 + 2; }
        if (lane < 19 && x.w > v) { v = x.w; ai = b0 + 3; }
    }
    #pragma unroll
    for (int o = 16; o; o >>= 1) {
        float ov = __shfl_xor_sync(0xffffffffu, v, o);
        int   oi = __shfl_xor_sync(0xffffffffu, ai, o);
        if (ov > v || (ov == v && oi < ai)) { v = ov; ai = oi; }
    }

    if (lane == 0) {
        out[OFF_SCORES + warp_id] = __expf(v - m) / s;
        out[OFF_LABELS + warp_id] = (float)ai;
        if (warp_id < NN) g_keep[warp_id] = (m > 0.0f);
    }
}

// ---------------------------------------------------------------------------
// Kernel C: one block of 512 threads per batch.
//  - Fused DDIM box update (uses g_keep from kernel A)
//  - Label-bucketed 1-D NMS, fully parallel:
//      stage -> counting sort by label -> rank-sort within group (thread per
//      element) -> 64-bit suppression masks (thread per element) -> bitmask
//      greedy (thread per group) -> output.
//    Serial O(k^2) fallback for any group with k>64 (never in practice).
// ---------------------------------------------------------------------------
__global__ __launch_bounds__(512)
void nms_boxes_kernel(const float* __restrict__ boxes_t,
                      const float* __restrict__ pb,
                      const float* __restrict__ noise,
                      const float* __restrict__ fresh,
                      const float* __restrict__ ac,
                      const int*   __restrict__ t_now_p,
                      const int*   __restrict__ t_next_p,
                      float* __restrict__ out)
{
    const int b   = blockIdx.x;
    const int tid = threadIdx.x;

    __shared__ float sx1[NN], sx2[NN], sw[NN];
    __shared__ unsigned long long skey[NN];
    __shared__ unsigned long long smask[NN];   // per sorted slot: suppression mask / flag
    __shared__ unsigned long long gsup[CC];
    __shared__ int   slab[NN];
    __shared__ short srank[NN];
    __shared__ short grouped[NN];              // unsorted group member lists
    __shared__ short sorted2[NN];              // sorted group member lists
    __shared__ int   hist[CC], offs[CC], cur[CC];

    if (tid < CC) hist[tid] = 0;
    __syncthreads();

    // DDIM scalars (same fp32 op sequence as reference)
    const int   t_now      = *t_now_p;
    const int   t_next     = *t_next_p;
    const float alpha      = ac[t_now];
    const float alpha_next = ac[t_next];
    const float sqrt_recip   = sqrtf(1.0f / alpha);
    const float sqrt_recipm1 = sqrtf(1.0f / alpha - 1.0f);
    const float sigma = sqrtf((1.0f - alpha / alpha_next) * (1.0f - alpha_next)
                              / (1.0f - alpha));
    const float ccoef = sqrtf(1.0f - alpha_next - sigma * sigma);
    const float sq_an = sqrtf(alpha_next);

    const float* pb5 = pb + (size_t)5 * BB * NN * 2;

    // ---- stage: box update + NMS inputs ----
    if (tid < NN) {
        const int n = tid;
        size_t base = ((size_t)b * NN + n) * 2;
        float c0 = pb5[base];
        float w0 = pb5[base + 1];

        int kp = g_keep[n];
        {
            float pn0 = (sqrt_recip * boxes_t[base]     - c0) / sqrt_recipm1;
            float pn1 = (sqrt_recip * boxes_t[base + 1] - w0) / sqrt_recipm1;
            float u0  = c0 * sq_an + ccoef * pn0 + sigma * noise[base];
            float u1  = w0 * sq_an + ccoef * pn1 + sigma * noise[base + 1];
            out[base]     = kp ? u0 : fresh[base];
            out[base + 1] = kp ? u1 : fresh[base + 1];
        }

        float w = fmaxf(w0, 0.0001f);
        sx1[n] = c0 - w * 0.5f;
        sx2[n] = c0 + w * 0.5f;
        sw[n]  = w;

        float sc = out[OFF_SCORES + b * NN + n];
        unsigned u = __float_as_uint(sc);   // scores > 0, so bits are order-preserving
        skey[n] = ((unsigned long long)(~u) << 32) | (unsigned)n;  // asc == (score desc, idx asc)
        int lab = (int)out[OFF_LABELS + b * NN + n];
        slab[n] = lab;
        atomicAdd(&hist[lab], 1);
    }
    __syncthreads();

    // ---- prefix sum over 80 label bins ----
    if (tid == 0) {
        int acc = 0;
        #pragma unroll 8
        for (int l = 0; l < CC; ++l) { offs[l] = acc; cur[l] = acc; acc += hist[l]; }
    }
    __syncthreads();

    // ---- counting-sort scatter (unsorted within group) ----
    if (tid < NN) {
        int pos = atomicAdd(&cur[slab[tid]], 1);
        grouped[pos] = (short)tid;
    }
    __syncthreads();

    // ---- rank-sort within group: thread per element ----
    if (tid < NN) {
        const int n = tid;
        int g = slab[n], base0 = offs[g], k = hist[g];
        unsigned long long my = skey[n];
        int r = 0;
        for (int i = 0; i < k; ++i)
            r += (skey[grouped[base0 + i]] < my);
        srank[n] = (short)r;
        sorted2[base0 + r] = (short)n;
    }
    __syncthreads();

    // ---- suppression masks: thread per element (k<=64 groups only) ----
    if (tid < NN) {
        const int n = tid;
        int g = slab[n], base0 = offs[g], k = hist[g];
        if (k <= 64) {
            int a = srank[n];
            float x1i = sx1[n], x2i = sx2[n], wi = sw[n];
            unsigned long long m = 0ull;
            for (int q = a + 1; q < k; ++q) {
                int j = sorted2[base0 + q];
                float inter = fmaxf(0.0f, fminf(x2i, sx2[j]) - fmaxf(x1i, sx1[j]));
                float uni   = wi + sw[j] - inter;
                if (inter / fmaxf(uni, 1e-9f) > 0.5f) m |= (1ull << q);
            }
            smask[base0 + a] = m;
        }
    }
    __syncthreads();

    // ---- greedy: thread per group ----
    if (tid < CC) {
        int k = hist[tid], base0 = offs[tid];
        unsigned long long sup = 0ull;
        if (k <= 64) {
            for (int a = 0; a < k; ++a)
                if (!((sup >> a) & 1ull)) sup |= smask[base0 + a];
        } else {
            // robust serial fallback (practically never taken): flags in smask
            for (int a = 0; a < k; ++a) smask[base0 + a] = 0ull;
            for (int a = 0; a < k; ++a) {
                if (smask[base0 + a]) continue;
                int i = sorted2[base0 + a];
                float x1i = sx1[i], x2i = sx2[i], wi = sw[i];
                for (int q = a + 1; q < k; ++q) {
                    int j = sorted2[base0 + q];
                    float inter = fmaxf(0.0f, fminf(x2i, sx2[j]) - fmaxf(x1i, sx1[j]));
                    float uni   = wi + sw[j] - inter;
                    if (inter / fmaxf(uni, 1e-9f) > 0.5f) smask[base0 + q] = 1ull;
                }
            }
        }
        gsup[tid] = sup;
    }
    __syncthreads();

    // ---- output keep mask ----
    if (tid < NN) {
        const int n = tid;
        int g = slab[n], k = hist[g];
        int a = srank[n];
        bool suppressed = (k <= 64) ? (((gsup[g] >> a) & 1ull) != 0ull)
                                    : (smask[offs[g] + a] != 0ull);
        out[OFF_KEEP + b * NN + n] = suppressed ? 0.0f : 1.0f;
    }
}

// ---------------------------------------------------------------------------
// Inputs (metadata order):
//  0 boxes_t          (128,500,2)    f32
//  1 predicted_class  (6,128,500,80) f32
//  2 predicted_boxes  (6,128,500,2)  f32
//  3 noise            (128,500,2)    f32
//  4 fresh_noise      (128,500,2)    f32
//  5 alphas_cumprod   (1000,)        f32
//  6 t_now            scalar         i32
//  7 t_next           scalar         i32
// ---------------------------------------------------------------------------
extern "C" void kernel_launch(void* const* d_in, const int* in_sizes, int n_in,
                              void* d_out, int out_size)
{
    const float* boxes_t = (const float*)d_in[0];
    const float* pc      = (const float*)d_in[1];
    const float* pb      = (const float*)d_in[2];
    const float* noise   = (const float*)d_in[3];
    const float* fresh   = (const float*)d_in[4];
    const float* ac      = (const float*)d_in[5];
    const int*   t_now   = (const int*)d_in[6];
    const int*   t_next  = (const int*)d_in[7];
    float* out = (float*)d_out;

    // Kernel A: 64000 rows, 1 warp each -> 8000 blocks of 256 threads
    int rows = BB * NN;
    int blocksA = (rows * 32 + 255) / 256;
    scores_kernel<<<blocksA, 256>>>(pc, out);

    // Kernel C: one block per batch (reads g_keep + scores/labels written by A)
    nms_boxes_kernel<<<BB, 512>>>(boxes_t, pb, noise, fresh, ac, t_now, t_next, out);
}

// round 9
// speedup vs baseline: 2.8957x; 1.4395x over previous
#include <cuda_runtime.h>
#include <math.h>

// Shapes (fixed by the problem)
#define BB 128
#define NN 500
#define CC 80
// Head index used = 5 (last of 6)

// d_out layout (float32, 320000 elems):
//   [0      : 128000) boxes_next (B,N,2)
//   [128000 : 192000) scores     (B,N)
//   [192000 : 256000) labels     (B,N) as float
//   [256000 : 320000) nms_keep   (B,N) as 0/1 float
#define OFF_SCORES 128000
#define OFF_LABELS 192000
#define OFF_KEEP   256000

__device__ int g_keep[512];  // keep mask computed from batch 0 (n < 500)

// ---------------------------------------------------------------------------
// Kernel A: 4 lanes per row, 8 rows per warp. Each lane loads 5 float4
// (stride-4 vec indices) so each LDG.128 covers 8 rows x 64B = 16 sectors
// (optimal). Reductions are 2-step shuffles within the 4-lane group.
// Outputs: softmax prob of argmax over first 79 classes, argmax label,
// and (batch 0 only) keep = max logit over all 80 > 0  <=> sigmoid > 0.5.
// ---------------------------------------------------------------------------
__global__ __launch_bounds__(256)
void scores_kernel(const float* __restrict__ pc, float* __restrict__ out)
{
    const int warp_global = (blockIdx.x * blockDim.x + threadIdx.x) >> 5;
    const int lane = threadIdx.x & 31;
    const int sub  = lane >> 2;   // row within this warp's 8
    const int q    = lane & 3;    // quarter of the row
    const int row  = warp_global * 8 + sub;
    if (row >= BB * NN) return;   // grid sized exactly; never taken

    const float4* rp = (const float4*)(pc + (size_t)5 * BB * NN * CC
                                          + (size_t)row * CC);
    // vec indices q, q+4, q+8, q+12, q+16 -> cols 4q+16i + {0..3}
    float4 a0 = __ldg(rp + q);
    float4 a1 = __ldg(rp + q + 4);
    float4 a2 = __ldg(rp + q + 8);
    float4 a3 = __ldg(rp + q + 12);
    float4 a4 = __ldg(rp + q + 16);

    // local max over ALL 20 values (includes col 79)
    float lmax = fmaxf(fmaxf(fmaxf(a0.x, a0.y), fmaxf(a0.z, a0.w)),
                 fmaxf(fmaxf(fmaxf(a1.x, a1.y), fmaxf(a1.z, a1.w)),
                 fmaxf(fmaxf(fmaxf(a2.x, a2.y), fmaxf(a2.z, a2.w)),
                 fmaxf(fmaxf(fmaxf(a3.x, a3.y), fmaxf(a3.z, a3.w)),
                 fmaxf(fmaxf(a4.x, a4.y), fmaxf(a4.z, a4.w))))));

    // local argmax over first 79 (exclude col 79 = q==3 lane's a4.w).
    // Ascending col order + strict '>' keeps the smallest index on ties.
    float v; int ai;
    const int c0 = 4 * q;
    v = a0.x; ai = c0;
#define ARGM(val, col) if ((val) > v) { v = (val); ai = (col); }
    ARGM(a0.y, c0 + 1) ARGM(a0.z, c0 + 2) ARGM(a0.w, c0 + 3)
    ARGM(a1.x, c0 + 16) ARGM(a1.y, c0 + 17) ARGM(a1.z, c0 + 18) ARGM(a1.w, c0 + 19)
    ARGM(a2.x, c0 + 32) ARGM(a2.y, c0 + 33) ARGM(a2.z, c0 + 34) ARGM(a2.w, c0 + 35)
    ARGM(a3.x, c0 + 48) ARGM(a3.y, c0 + 49) ARGM(a3.z, c0 + 50) ARGM(a3.w, c0 + 51)
    ARGM(a4.x, c0 + 64) ARGM(a4.y, c0 + 65) ARGM(a4.z, c0 + 66)
    if (q != 3) ARGM(a4.w, c0 + 67)
#undef ARGM

    // cross-lane reductions within the 4-lane group (xor 1, xor 2)
    float m = lmax;
    m = fmaxf(m, __shfl_xor_sync(0xffffffffu, m, 1));
    m = fmaxf(m, __shfl_xor_sync(0xffffffffu, m, 2));

    #pragma unroll
    for (int o = 1; o <= 2; o <<= 1) {
        float ov = __shfl_xor_sync(0xffffffffu, v, o);
        int   oi = __shfl_xor_sync(0xffffffffu, ai, o);
        if (ov > v || (ov == v && oi < ai)) { v = ov; ai = oi; }
    }

    // exp sum over all 20 local values, then 2-step reduce
    float s = __expf(a0.x - m) + __expf(a0.y - m) + __expf(a0.z - m) + __expf(a0.w - m)
            + __expf(a1.x - m) + __expf(a1.y - m) + __expf(a1.z - m) + __expf(a1.w - m)
            + __expf(a2.x - m) + __expf(a2.y - m) + __expf(a2.z - m) + __expf(a2.w - m)
            + __expf(a3.x - m) + __expf(a3.y - m) + __expf(a3.z - m) + __expf(a3.w - m)
            + __expf(a4.x - m) + __expf(a4.y - m) + __expf(a4.z - m) + __expf(a4.w - m);
    s += __shfl_xor_sync(0xffffffffu, s, 1);
    s += __shfl_xor_sync(0xffffffffu, s, 2);

    if (q == 0) {
        out[OFF_SCORES + row] = __expf(v - m) / s;
        out[OFF_LABELS + row] = (float)ai;
        if (row < NN) g_keep[row] = (m > 0.0f);
    }
}

// ---------------------------------------------------------------------------
// Kernel C: one block of 512 threads per batch. Thread tid owns element
// n=tid for ALL phases -> key/box/label/rank persist in registers.
//  stage (float2, DDIM update + key) -> count -> prefix -> scatter KEYS into
//  grouped order -> rank by sequential LDS scan -> build sorted coord arrays
//  from registers -> suppression masks over sequential arrays -> bitmask
//  greedy per group -> output. No pointer-chasing indirection anywhere.
//  Serial O(k^2) fallback for any group with k>64 (never in practice).
// ---------------------------------------------------------------------------
__global__ __launch_bounds__(512)
void nms_boxes_kernel(const float* __restrict__ boxes_t,
                      const float* __restrict__ pb,
                      const float* __restrict__ noise,
                      const float* __restrict__ fresh,
                      const float* __restrict__ ac,
                      const int*   __restrict__ t_now_p,
                      const int*   __restrict__ t_next_p,
                      float* __restrict__ out)
{
    const int b   = blockIdx.x;
    const int tid = threadIdx.x;

    __shared__ unsigned long long gkey[NN];   // keys in grouped (unsorted) order
    __shared__ float ss1[NN], ss2[NN], ssw[NN];  // coords in sorted order
    __shared__ unsigned long long smask[NN];  // per sorted slot: mask / flag
    __shared__ unsigned long long gsup[CC];
    __shared__ int hist[CC], offs[CC], cur[CC];

    if (tid < CC) hist[tid] = 0;
    __syncthreads();

    // DDIM scalars (same fp32 op sequence as reference)
    const int   t_now      = *t_now_p;
    const int   t_next     = *t_next_p;
    const float alpha      = ac[t_now];
    const float alpha_next = ac[t_next];
    const float sqrt_recip   = sqrtf(1.0f / alpha);
    const float sqrt_recipm1 = sqrtf(1.0f / alpha - 1.0f);
    const float sigma = sqrtf((1.0f - alpha / alpha_next) * (1.0f - alpha_next)
                              / (1.0f - alpha));
    const float ccoef = sqrtf(1.0f - alpha_next - sigma * sigma);
    const float sq_an = sqrtf(alpha_next);

    // per-thread persistent state
    float x1 = 0.0f, x2 = 0.0f, w = 0.0f;
    unsigned long long key = 0ull;
    int g = 0;

    // ---- stage: box update + NMS inputs (float2-vectorized) ----
    if (tid < NN) {
        const size_t idx = (size_t)b * NN + tid;
        const float2 bt = ((const float2*)boxes_t)[idx];
        const float2 bs = ((const float2*)(pb + (size_t)5 * BB * NN * 2))[idx];
        const float2 nz = ((const float2*)noise)[idx];
        const float2 fz = ((const float2*)fresh)[idx];
        const int    kp = g_keep[tid];

        float pn0 = (sqrt_recip * bt.x - bs.x) / sqrt_recipm1;
        float pn1 = (sqrt_recip * bt.y - bs.y) / sqrt_recipm1;
        float2 u;
        u.x = kp ? bs.x * sq_an + ccoef * pn0 + sigma * nz.x : fz.x;
        u.y = kp ? bs.y * sq_an + ccoef * pn1 + sigma * nz.y : fz.y;
        ((float2*)out)[idx] = u;

        w  = fmaxf(bs.y, 0.0001f);
        x1 = bs.x - w * 0.5f;
        x2 = bs.x + w * 0.5f;

        float sc = out[OFF_SCORES + idx];
        unsigned uu = __float_as_uint(sc);  // scores > 0: bits order-preserving
        key = ((unsigned long long)(~uu) << 32) | (unsigned)tid; // asc == (score desc, idx asc)
        g = (int)out[OFF_LABELS + idx];
        atomicAdd(&hist[g], 1);
    }
    __syncthreads();

    // ---- prefix sum over 80 label bins ----
    if (tid == 0) {
        int acc = 0;
        #pragma unroll 8
        for (int l = 0; l < CC; ++l) { offs[l] = acc; cur[l] = acc; acc += hist[l]; }
    }
    __syncthreads();

    // ---- scatter keys into grouped order ----
    if (tid < NN) {
        int pos = atomicAdd(&cur[g], 1);
        gkey[pos] = key;
    }
    __syncthreads();

    // ---- rank via sequential scan; build sorted coord arrays from registers --
    int base0 = 0, k = 0, r = 0;
    if (tid < NN) {
        base0 = offs[g];
        k     = hist[g];
        for (int i = 0; i < k; ++i)
            r += (gkey[base0 + i] < key);
        ss1[base0 + r] = x1;
        ss2[base0 + r] = x2;
        ssw[base0 + r] = w;
    }
    __syncthreads();

    // ---- suppression masks (sequential-address LDS, no indirection) ----
    if (tid < NN && k <= 64) {
        unsigned long long m = 0ull;
        for (int qq = r + 1; qq < k; ++qq) {
            float inter = fmaxf(0.0f, fminf(x2, ss2[base0 + qq])
                                    - fmaxf(x1, ss1[base0 + qq]));
            float uni   = w + ssw[base0 + qq] - inter;
            if (inter / fmaxf(uni, 1e-9f) > 0.5f) m |= (1ull << qq);
        }
        smask[base0 + r] = m;
    }
    __syncthreads();

    // ---- greedy: thread per group ----
    if (tid < CC) {
        int kk = hist[tid], bb0 = offs[tid];
        unsigned long long sup = 0ull;
        if (kk <= 64) {
            for (int a = 0; a < kk; ++a)
                if (!((sup >> a) & 1ull)) sup |= smask[bb0 + a];
        } else {
            // robust serial fallback (practically never taken): flags in smask
            for (int a = 0; a < kk; ++a) smask[bb0 + a] = 0ull;
            for (int a = 0; a < kk; ++a) {
                if (smask[bb0 + a]) continue;
                float X1 = ss1[bb0 + a], X2 = ss2[bb0 + a], W = ssw[bb0 + a];
                for (int qq = a + 1; qq < kk; ++qq) {
                    float inter = fmaxf(0.0f, fminf(X2, ss2[bb0 + qq])
                                            - fmaxf(X1, ss1[bb0 + qq]));
                    float uni   = W + ssw[bb0 + qq] - inter;
                    if (inter / fmaxf(uni, 1e-9f) > 0.5f) smask[bb0 + qq] = 1ull;
                }
            }
        }
        gsup[tid] = sup;
    }
    __syncthreads();

    // ---- output keep mask (rank + group still in registers) ----
    if (tid < NN) {
        bool suppressed = (k <= 64) ? (((gsup[g] >> r) & 1ull) != 0ull)
                                    : (smask[base0 + r] != 0ull);
        out[OFF_KEEP + (size_t)b * NN + tid] = suppressed ? 0.0f : 1.0f;
    }
}

// ---------------------------------------------------------------------------
// Inputs (metadata order):
//  0 boxes_t          (128,500,2)    f32
//  1 predicted_class  (6,128,500,80) f32
//  2 predicted_boxes  (6,128,500,2)  f32
//  3 noise            (128,500,2)    f32
//  4 fresh_noise      (128,500,2)    f32
//  5 alphas_cumprod   (1000,)        f32
//  6 t_now            scalar         i32
//  7 t_next           scalar         i32
// ---------------------------------------------------------------------------
extern "C" void kernel_launch(void* const* d_in, const int* in_sizes, int n_in,
                              void* d_out, int out_size)
{
    const float* boxes_t = (const float*)d_in[0];
    const float* pc      = (const float*)d_in[1];
    const float* pb      = (const float*)d_in[2];
    const float* noise   = (const float*)d_in[3];
    const float* fresh   = (const float*)d_in[4];
    const float* ac      = (const float*)d_in[5];
    const int*   t_now   = (const int*)d_in[6];
    const int*   t_next  = (const int*)d_in[7];
    float* out = (float*)d_out;

    // Kernel A: 64000 rows, 8 rows per warp, 8 warps per block -> 1000 blocks
    scores_kernel<<<1000, 256>>>(pc, out);

    // Kernel C: one block per batch (reads g_keep + scores/labels written by A)
    nms_boxes_kernel<<<BB, 512>>>(boxes_t, pb, noise, fresh, ac, t_now, t_next, out);
}

// round 10
// speedup vs baseline: 2.9507x; 1.0190x over previous
#include <cuda_runtime.h>
#include <math.h>

// Shapes (fixed by the problem)
#define BB 128
#define NN 500
#define CC 80
// Head index used = 5 (last of 6)

// d_out layout (float32, 320000 elems):
//   [0      : 128000) boxes_next (B,N,2)
//   [128000 : 192000) scores     (B,N)
//   [192000 : 256000) labels     (B,N) as float
//   [256000 : 320000) nms_keep   (B,N) as 0/1 float
#define OFF_SCORES 128000
#define OFF_LABELS 192000
#define OFF_KEEP   256000

// ---------------------------------------------------------------------------
// ONE fused kernel: one block of 512 threads per batch.
//   top:     preload box-update operands + DDIM scalar chain (latency hidden)
//   phase K: batch-0 keep mask (max logit > 0), 4-lane/8-row pattern, L2-hot
//   phase S: own-batch softmax score + argmax label -> shared (+ global out)
//   stage:   DDIM box update + NMS staging (keys, coords, label histogram)
//   NMS:     prefix -> scatter keys -> rank-sort -> 64-bit suppression masks
//            -> bitmask greedy per label group -> keep output
//   (serial O(k^2) fallback for any label group with k>64 — never in practice)
// ---------------------------------------------------------------------------
__global__ __launch_bounds__(512)
void fused_kernel(const float* __restrict__ boxes_t,
                  const float* __restrict__ pc,
                  const float* __restrict__ pb,
                  const float* __restrict__ noise,
                  const float* __restrict__ fresh,
                  const float* __restrict__ ac,
                  const int*   __restrict__ t_now_p,
                  const int*   __restrict__ t_next_p,
                  float* __restrict__ out)
{
    const int b   = blockIdx.x;
    const int tid = threadIdx.x;
    const int q        = tid & 3;   // quarter of a row
    const int slot_b   = tid >> 2;  // row-slot 0..127 per pass

    __shared__ int      skeep[NN];            // batch-0 keep mask
    __shared__ unsigned sukey[NN];            // ~bits(score) per row
    __shared__ int      slabel[NN];           // argmax label per row
    __shared__ unsigned long long gkey[NN];   // keys in grouped (unsorted) order
    __shared__ float ss1[NN], ss2[NN], ssw[NN];  // coords in sorted order
    __shared__ unsigned long long smask[NN];  // per sorted slot: mask / flag
    __shared__ unsigned long long gsup[CC];
    __shared__ int hist[CC], offs[CC], cur[CC];

    if (tid < CC) hist[tid] = 0;

    // ---- early independent loads: box-update operands (consumed in stage) --
    float2 bt, bs, nz, fz;
    if (tid < NN) {
        const size_t idx = (size_t)b * NN + tid;
        bt = ((const float2*)boxes_t)[idx];
        bs = ((const float2*)(pb + (size_t)5 * BB * NN * 2))[idx];
        nz = ((const float2*)noise)[idx];
        fz = ((const float2*)fresh)[idx];
    }
    // DDIM scalar chain (dependent loads — issued early, hidden under K/S)
    const int   t_now      = *t_now_p;
    const int   t_next     = *t_next_p;
    const float alpha      = ac[t_now];
    const float alpha_next = ac[t_next];

    const float* pc5 = pc + (size_t)5 * BB * NN * CC;

    // ---- phase K: batch-0 keep mask (max over all 80 logits > 0) ----------
    #pragma unroll
    for (int p = 0; p < 4; ++p) {
        int slot  = p * 128 + slot_b;
        int slotc = slot < NN ? slot : NN - 1;   // clamp: all lanes active
        const float4* rp = (const float4*)(pc5 + (size_t)slotc * CC);
        float4 a0 = __ldg(rp + q);
        float4 a1 = __ldg(rp + q + 4);
        float4 a2 = __ldg(rp + q + 8);
        float4 a3 = __ldg(rp + q + 12);
        float4 a4 = __ldg(rp + q + 16);
        float m = fmaxf(fmaxf(fmaxf(a0.x, a0.y), fmaxf(a0.z, a0.w)),
                  fmaxf(fmaxf(fmaxf(a1.x, a1.y), fmaxf(a1.z, a1.w)),
                  fmaxf(fmaxf(fmaxf(a2.x, a2.y), fmaxf(a2.z, a2.w)),
                  fmaxf(fmaxf(fmaxf(a3.x, a3.y), fmaxf(a3.z, a3.w)),
                  fmaxf(fmaxf(a4.x, a4.y), fmaxf(a4.z, a4.w))))));
        m = fmaxf(m, __shfl_xor_sync(0xffffffffu, m, 1));
        m = fmaxf(m, __shfl_xor_sync(0xffffffffu, m, 2));
        if (q == 0 && slot < NN) skeep[slot] = (m > 0.0f);
    }

    // ---- phase S: own-batch score + label ---------------------------------
    #pragma unroll
    for (int p = 0; p < 4; ++p) {
        int slot  = p * 128 + slot_b;
        int slotc = slot < NN ? slot : NN - 1;
        const float4* rp = (const float4*)(pc5 + ((size_t)b * NN + slotc) * CC);
        float4 a0 = __ldg(rp + q);
        float4 a1 = __ldg(rp + q + 4);
        float4 a2 = __ldg(rp + q + 8);
        float4 a3 = __ldg(rp + q + 12);
        float4 a4 = __ldg(rp + q + 16);

        // max over all 80 (softmax normalization)
        float lmax = fmaxf(fmaxf(fmaxf(a0.x, a0.y), fmaxf(a0.z, a0.w)),
                     fmaxf(fmaxf(fmaxf(a1.x, a1.y), fmaxf(a1.z, a1.w)),
                     fmaxf(fmaxf(fmaxf(a2.x, a2.y), fmaxf(a2.z, a2.w)),
                     fmaxf(fmaxf(fmaxf(a3.x, a3.y), fmaxf(a3.z, a3.w)),
                     fmaxf(fmaxf(a4.x, a4.y), fmaxf(a4.z, a4.w))))));

        // local argmax over first 79 (exclude col 79 = q==3 lane's a4.w).
        // Ascending col order + strict '>' keeps the smallest index on ties.
        float v; int ai;
        const int c0 = 4 * q;
        v = a0.x; ai = c0;
#define ARGM(val, col) if ((val) > v) { v = (val); ai = (col); }
        ARGM(a0.y, c0 + 1) ARGM(a0.z, c0 + 2) ARGM(a0.w, c0 + 3)
        ARGM(a1.x, c0 + 16) ARGM(a1.y, c0 + 17) ARGM(a1.z, c0 + 18) ARGM(a1.w, c0 + 19)
        ARGM(a2.x, c0 + 32) ARGM(a2.y, c0 + 33) ARGM(a2.z, c0 + 34) ARGM(a2.w, c0 + 35)
        ARGM(a3.x, c0 + 48) ARGM(a3.y, c0 + 49) ARGM(a3.z, c0 + 50) ARGM(a3.w, c0 + 51)
        ARGM(a4.x, c0 + 64) ARGM(a4.y, c0 + 65) ARGM(a4.z, c0 + 66)
        if (q != 3) ARGM(a4.w, c0 + 67)
#undef ARGM

        float m = lmax;
        m = fmaxf(m, __shfl_xor_sync(0xffffffffu, m, 1));
        m = fmaxf(m, __shfl_xor_sync(0xffffffffu, m, 2));

        #pragma unroll
        for (int o = 1; o <= 2; o <<= 1) {
            float ov = __shfl_xor_sync(0xffffffffu, v, o);
            int   oi = __shfl_xor_sync(0xffffffffu, ai, o);
            if (ov > v || (ov == v && oi < ai)) { v = ov; ai = oi; }
        }

        float s = __expf(a0.x - m) + __expf(a0.y - m) + __expf(a0.z - m) + __expf(a0.w - m)
                + __expf(a1.x - m) + __expf(a1.y - m) + __expf(a1.z - m) + __expf(a1.w - m)
                + __expf(a2.x - m) + __expf(a2.y - m) + __expf(a2.z - m) + __expf(a2.w - m)
                + __expf(a3.x - m) + __expf(a3.y - m) + __expf(a3.z - m) + __expf(a3.w - m)
                + __expf(a4.x - m) + __expf(a4.y - m) + __expf(a4.z - m) + __expf(a4.w - m);
        s += __shfl_xor_sync(0xffffffffu, s, 1);
        s += __shfl_xor_sync(0xffffffffu, s, 2);

        if (q == 0 && slot < NN) {
            float sc = __expf(v - m) / s;
            out[OFF_SCORES + (size_t)b * NN + slot] = sc;
            out[OFF_LABELS + (size_t)b * NN + slot] = (float)ai;
            sukey[slot]  = ~__float_as_uint(sc);  // scores > 0: order-preserving
            slabel[slot] = ai;
        }
    }

    // DDIM scalars (same fp32 op sequence as reference)
    const float sqrt_recip   = sqrtf(1.0f / alpha);
    const float sqrt_recipm1 = sqrtf(1.0f / alpha - 1.0f);
    const float sigma = sqrtf((1.0f - alpha / alpha_next) * (1.0f - alpha_next)
                              / (1.0f - alpha));
    const float ccoef = sqrtf(1.0f - alpha_next - sigma * sigma);
    const float sq_an = sqrtf(alpha_next);

    __syncthreads();   // skeep / sukey / slabel / hist=0 visible

    // ---- stage: box update + NMS staging ----------------------------------
    float x1 = 0.0f, x2 = 0.0f, w = 0.0f;
    unsigned long long key = 0ull;
    int g = 0;
    if (tid < NN) {
        const size_t idx = (size_t)b * NN + tid;
        const int kp = skeep[tid];
        float pn0 = (sqrt_recip * bt.x - bs.x) / sqrt_recipm1;
        float pn1 = (sqrt_recip * bt.y - bs.y) / sqrt_recipm1;
        float2 u;
        u.x = kp ? bs.x * sq_an + ccoef * pn0 + sigma * nz.x : fz.x;
        u.y = kp ? bs.y * sq_an + ccoef * pn1 + sigma * nz.y : fz.y;
        ((float2*)out)[idx] = u;

        w  = fmaxf(bs.y, 0.0001f);
        x1 = bs.x - w * 0.5f;
        x2 = bs.x + w * 0.5f;

        key = ((unsigned long long)sukey[tid] << 32) | (unsigned)tid; // asc == (score desc, idx asc)
        g   = slabel[tid];
        atomicAdd(&hist[g], 1);
    }
    __syncthreads();

    // ---- prefix sum over 80 label bins ----
    if (tid == 0) {
        int acc = 0;
        #pragma unroll 8
        for (int l = 0; l < CC; ++l) { offs[l] = acc; cur[l] = acc; acc += hist[l]; }
    }
    __syncthreads();

    // ---- scatter keys into grouped order ----
    if (tid < NN) {
        int pos = atomicAdd(&cur[g], 1);
        gkey[pos] = key;
    }
    __syncthreads();

    // ---- rank via sequential scan; build sorted coord arrays from registers --
    int base0 = 0, k = 0, r = 0;
    if (tid < NN) {
        base0 = offs[g];
        k     = hist[g];
        for (int i = 0; i < k; ++i)
            r += (gkey[base0 + i] < key);
        ss1[base0 + r] = x1;
        ss2[base0 + r] = x2;
        ssw[base0 + r] = w;
    }
    __syncthreads();

    // ---- suppression masks (sequential-address LDS, no indirection) ----
    if (tid < NN && k <= 64) {
        unsigned long long m = 0ull;
        for (int qq = r + 1; qq < k; ++qq) {
            float inter = fmaxf(0.0f, fminf(x2, ss2[base0 + qq])
                                    - fmaxf(x1, ss1[base0 + qq]));
            float uni   = w + ssw[base0 + qq] - inter;
            if (inter / fmaxf(uni, 1e-9f) > 0.5f) m |= (1ull << qq);
        }
        smask[base0 + r] = m;
    }
    __syncthreads();

    // ---- greedy: thread per group ----
    if (tid < CC) {
        int kk = hist[tid], bb0 = offs[tid];
        unsigned long long sup = 0ull;
        if (kk <= 64) {
            for (int a = 0; a < kk; ++a)
                if (!((sup >> a) & 1ull)) sup |= smask[bb0 + a];
        } else {
            // robust serial fallback (practically never taken): flags in smask
            for (int a = 0; a < kk; ++a) smask[bb0 + a] = 0ull;
            for (int a = 0; a < kk; ++a) {
                if (smask[bb0 + a]) continue;
                float X1 = ss1[bb0 + a], X2 = ss2[bb0 + a], W = ssw[bb0 + a];
                for (int qq = a + 1; qq < kk; ++qq) {
                    float inter = fmaxf(0.0f, fminf(X2, ss2[bb0 + qq])
                                            - fmaxf(X1, ss1[bb0 + qq]));
                    float uni   = W + ssw[bb0 + qq] - inter;
                    if (inter / fmaxf(uni, 1e-9f) > 0.5f) smask[bb0 + qq] = 1ull;
                }
            }
        }
        gsup[tid] = sup;
    }
    __syncthreads();

    // ---- output keep mask (rank + group still in registers) ----
    if (tid < NN) {
        bool suppressed = (k <= 64) ? (((gsup[g] >> r) & 1ull) != 0ull)
                                    : (smask[base0 + r] != 0ull);
        out[OFF_KEEP + (size_t)b * NN + tid] = suppressed ? 0.0f : 1.0f;
    }
}

// ---------------------------------------------------------------------------
// Inputs (metadata order):
//  0 boxes_t          (128,500,2)    f32
//  1 predicted_class  (6,128,500,80) f32
//  2 predicted_boxes  (6,128,500,2)  f32
//  3 noise            (128,500,2)    f32
//  4 fresh_noise      (128,500,2)    f32
//  5 alphas_cumprod   (1000,)        f32
//  6 t_now            scalar         i32
//  7 t_next           scalar         i32
// ---------------------------------------------------------------------------
extern "C" void kernel_launch(void* const* d_in, const int* in_sizes, int n_in,
                              void* d_out, int out_size)
{
    const float* boxes_t = (const float*)d_in[0];
    const float* pc      = (const float*)d_in[1];
    const float* pb      = (const float*)d_in[2];
    const float* noise   = (const float*)d_in[3];
    const float* fresh   = (const float*)d_in[4];
    const float* ac      = (const float*)d_in[5];
    const int*   t_now   = (const int*)d_in[6];
    const int*   t_next  = (const int*)d_in[7];
    float* out = (float*)d_out;

    fused_kernel<<<BB, 512>>>(boxes_t, pc, pb, noise, fresh, ac, t_now, t_next, out);
}

// round 14
// speedup vs baseline: 2.9563x; 1.0019x over previous
#include <cuda_runtime.h>
#include <math.h>

// Shapes (fixed by the problem)
#define BB 128
#define NN 500
#define CC 80
// Head index used = 5 (last of 6)

// d_out layout (float32, 320000 elems):
//   [0      : 128000) boxes_next (B,N,2)
//   [128000 : 192000) scores     (B,N)
//   [192000 : 256000) labels     (B,N) as float
//   [256000 : 320000) nms_keep   (B,N) as 0/1 float
#define OFF_SCORES 128000
#define OFF_LABELS 192000
#define OFF_KEEP   256000

// ---------------------------------------------------------------------------
// ONE fused kernel: one block of 512 threads per batch.
// Score phases are software-pipelined: each super-pass p issues the own-batch
// DRAM loads for pass p+1 AND the batch-0 L2 loads for pass p before doing
// any reduction, so each warp keeps ~15 LDG.128 in flight (MLP-driven DRAM
// throughput). S-phase reduction arithmetic is bit-identical to R9.
// NMS tail: label-bucketed rank-sort + 64-bit suppression masks + bitmask
// greedy per group (serial O(k^2) fallback for k>64 — never in practice).
// ---------------------------------------------------------------------------
__global__ __launch_bounds__(512)
void fused_kernel(const float* __restrict__ boxes_t,
                  const float* __restrict__ pc,
                  const float* __restrict__ pb,
                  const float* __restrict__ noise,
                  const float* __restrict__ fresh,
                  const float* __restrict__ ac,
                  const int*   __restrict__ t_now_p,
                  const int*   __restrict__ t_next_p,
                  float* __restrict__ out)
{
    const int b      = blockIdx.x;
    const int tid    = threadIdx.x;
    const int q      = tid & 3;   // quarter of a row
    const int slot_b = tid >> 2;  // row-slot 0..127 per pass

    __shared__ int      skeep[NN];            // batch-0 keep mask
    __shared__ unsigned sukey[NN];            // ~bits(score) per row
    __shared__ int      slabel[NN];           // argmax label per row
    __shared__ unsigned long long gkey[NN];   // keys in grouped (unsorted) order
    __shared__ float ss1[NN], ss2[NN], ssw[NN];  // coords in sorted order
    __shared__ unsigned long long smask[NN];  // per sorted slot: mask / flag
    __shared__ unsigned long long gsup[CC];
    __shared__ int hist[CC], offs[CC], cur[CC];

    if (tid < CC) hist[tid] = 0;

    // ---- early independent loads: box-update operands (consumed in stage) --
    float2 bt, bs, nz, fz;
    if (tid < NN) {
        const size_t idx = (size_t)b * NN + tid;
        bt = ((const float2*)boxes_t)[idx];
        bs = ((const float2*)(pb + (size_t)5 * BB * NN * 2))[idx];
        nz = ((const float2*)noise)[idx];
        fz = ((const float2*)fresh)[idx];
    }
    // DDIM scalar chain (dependent loads — issued early)
    const int   t_now      = *t_now_p;
    const int   t_next     = *t_next_p;
    const float alpha      = ac[t_now];
    const float alpha_next = ac[t_next];

    const float* pc5 = pc + (size_t)5 * BB * NN * CC;

    // ---- pipelined score phases ----
    float4 sA[5], sB[5], kv[5];

    // prologue: own-batch (S) loads for pass 0
    {
        int slot  = slot_b;
        int slotc = slot < NN ? slot : NN - 1;
        const float4* rp = (const float4*)(pc5 + ((size_t)b * NN + slotc) * CC);
        #pragma unroll
        for (int i = 0; i < 5; ++i) sA[i] = __ldg(rp + q + 4 * i);
    }

    #pragma unroll
    for (int p = 0; p < 4; ++p) {
        float4* curb = (p & 1) ? sB : sA;
        float4* nxtb = (p & 1) ? sA : sB;

        // issue S loads for pass p+1 (DRAM) first
        if (p < 3) {
            int slot  = (p + 1) * 128 + slot_b;
            int slotc = slot < NN ? slot : NN - 1;
            const float4* rp = (const float4*)(pc5 + ((size_t)b * NN + slotc) * CC);
            #pragma unroll
            for (int i = 0; i < 5; ++i) nxtb[i] = __ldg(rp + q + 4 * i);
        }
        // issue K loads for pass p (batch 0, L2-broadcast)
        {
            int slot  = p * 128 + slot_b;
            int slotc = slot < NN ? slot : NN - 1;
            const float4* rp = (const float4*)(pc5 + (size_t)slotc * CC);
            #pragma unroll
            for (int i = 0; i < 5; ++i) kv[i] = __ldg(rp + q + 4 * i);
        }

        const int slot = p * 128 + slot_b;

        // ---- reduce K: batch-0 keep = (max over all 80 logits) > 0 ----
        {
            float m = fmaxf(fmaxf(fmaxf(kv[0].x, kv[0].y), fmaxf(kv[0].z, kv[0].w)),
                      fmaxf(fmaxf(fmaxf(kv[1].x, kv[1].y), fmaxf(kv[1].z, kv[1].w)),
                      fmaxf(fmaxf(fmaxf(kv[2].x, kv[2].y), fmaxf(kv[2].z, kv[2].w)),
                      fmaxf(fmaxf(fmaxf(kv[3].x, kv[3].y), fmaxf(kv[3].z, kv[3].w)),
                      fmaxf(fmaxf(kv[4].x, kv[4].y), fmaxf(kv[4].z, kv[4].w))))));
            m = fmaxf(m, __shfl_xor_sync(0xffffffffu, m, 1));
            m = fmaxf(m, __shfl_xor_sync(0xffffffffu, m, 2));
            if (q == 0 && slot < NN) skeep[slot] = (m > 0.0f);
        }

        // ---- reduce S: softmax score + argmax label (bit-identical to R9) --
        {
            float4 a0 = curb[0], a1 = curb[1], a2 = curb[2], a3 = curb[3], a4 = curb[4];

            float lmax = fmaxf(fmaxf(fmaxf(a0.x, a0.y), fmaxf(a0.z, a0.w)),
                         fmaxf(fmaxf(fmaxf(a1.x, a1.y), fmaxf(a1.z, a1.w)),
                         fmaxf(fmaxf(fmaxf(a2.x, a2.y), fmaxf(a2.z, a2.w)),
                         fmaxf(fmaxf(fmaxf(a3.x, a3.y), fmaxf(a3.z, a3.w)),
                         fmaxf(fmaxf(a4.x, a4.y), fmaxf(a4.z, a4.w))))));

            // local argmax over first 79 (exclude col 79 = q==3 lane's a4.w).
            float v; int ai;
            const int c0 = 4 * q;
            v = a0.x; ai = c0;
#define ARGM(val, col) if ((val) > v) { v = (val); ai = (col); }
            ARGM(a0.y, c0 + 1) ARGM(a0.z, c0 + 2) ARGM(a0.w, c0 + 3)
            ARGM(a1.x, c0 + 16) ARGM(a1.y, c0 + 17) ARGM(a1.z, c0 + 18) ARGM(a1.w, c0 + 19)
            ARGM(a2.x, c0 + 32) ARGM(a2.y, c0 + 33) ARGM(a2.z, c0 + 34) ARGM(a2.w, c0 + 35)
            ARGM(a3.x, c0 + 48) ARGM(a3.y, c0 + 49) ARGM(a3.z, c0 + 50) ARGM(a3.w, c0 + 51)
            ARGM(a4.x, c0 + 64) ARGM(a4.y, c0 + 65) ARGM(a4.z, c0 + 66)
            if (q != 3) ARGM(a4.w, c0 + 67)
#undef ARGM

            float m = lmax;
            m = fmaxf(m, __shfl_xor_sync(0xffffffffu, m, 1));
            m = fmaxf(m, __shfl_xor_sync(0xffffffffu, m, 2));

            #pragma unroll
            for (int o = 1; o <= 2; o <<= 1) {
                float ov = __shfl_xor_sync(0xffffffffu, v, o);
                int   oi = __shfl_xor_sync(0xffffffffu, ai, o);
                if (ov > v || (ov == v && oi < ai)) { v = ov; ai = oi; }
            }

            float s = __expf(a0.x - m) + __expf(a0.y - m) + __expf(a0.z - m) + __expf(a0.w - m)
                    + __expf(a1.x - m) + __expf(a1.y - m) + __expf(a1.z - m) + __expf(a1.w - m)
                    + __expf(a2.x - m) + __expf(a2.y - m) + __expf(a2.z - m) + __expf(a2.w - m)
                    + __expf(a3.x - m) + __expf(a3.y - m) + __expf(a3.z - m) + __expf(a3.w - m)
                    + __expf(a4.x - m) + __expf(a4.y - m) + __expf(a4.z - m) + __expf(a4.w - m);
            s += __shfl_xor_sync(0xffffffffu, s, 1);
            s += __shfl_xor_sync(0xffffffffu, s, 2);

            if (q == 0 && slot < NN) {
                float sc = __expf(v - m) / s;
                out[OFF_SCORES + (size_t)b * NN + slot] = sc;
                out[OFF_LABELS + (size_t)b * NN + slot] = (float)ai;
                sukey[slot]  = ~__float_as_uint(sc);  // scores > 0: order-preserving
                slabel[slot] = ai;
            }
        }
    }

    // DDIM scalars (same fp32 op sequence as reference)
    const float sqrt_recip   = sqrtf(1.0f / alpha);
    const float sqrt_recipm1 = sqrtf(1.0f / alpha - 1.0f);
    const float sigma = sqrtf((1.0f - alpha / alpha_next) * (1.0f - alpha_next)
                              / (1.0f - alpha));
    const float ccoef = sqrtf(1.0f - alpha_next - sigma * sigma);
    const float sq_an = sqrtf(alpha_next);

    __syncthreads();   // skeep / sukey / slabel / hist=0 visible

    // ---- stage: box update + NMS staging ----------------------------------
    float x1 = 0.0f, x2 = 0.0f, w = 0.0f;
    unsigned long long key = 0ull;
    int g = 0;
    if (tid < NN) {
        const size_t idx = (size_t)b * NN + tid;
        const int kp = skeep[tid];
        float pn0 = (sqrt_recip * bt.x - bs.x) / sqrt_recipm1;
        float pn1 = (sqrt_recip * bt.y - bs.y) / sqrt_recipm1;
        float2 u;
        u.x = kp ? bs.x * sq_an + ccoef * pn0 + sigma * nz.x : fz.x;
        u.y = kp ? bs.y * sq_an + ccoef * pn1 + sigma * nz.y : fz.y;
        ((float2*)out)[idx] = u;

        w  = fmaxf(bs.y, 0.0001f);
        x1 = bs.x - w * 0.5f;
        x2 = bs.x + w * 0.5f;

        key = ((unsigned long long)sukey[tid] << 32) | (unsigned)tid; // asc == (score desc, idx asc)
        g   = slabel[tid];
        atomicAdd(&hist[g], 1);
    }
    __syncthreads();

    // ---- prefix sum over 80 label bins: parallel per-thread ----
    if (tid < CC) {
        int acc = 0;
        for (int l = 0; l < tid; ++l) acc += hist[l];
        offs[tid] = acc;
        cur[tid]  = acc;
    }
    __syncthreads();

    // ---- scatter keys into grouped order ----
    if (tid < NN) {
        int pos = atomicAdd(&cur[g], 1);
        gkey[pos] = key;
    }
    __syncthreads();

    // ---- rank via sequential scan; build sorted coord arrays from registers --
    int base0 = 0, k = 0, r = 0;
    if (tid < NN) {
        base0 = offs[g];
        k     = hist[g];
        for (int i = 0; i < k; ++i)
            r += (gkey[base0 + i] < key);
        ss1[base0 + r] = x1;
        ss2[base0 + r] = x2;
        ssw[base0 + r] = w;
    }
    __syncthreads();

    // ---- suppression masks (sequential-address LDS, no indirection) ----
    if (tid < NN && k <= 64) {
        unsigned long long m = 0ull;
        for (int qq = r + 1; qq < k; ++qq) {
            float inter = fmaxf(0.0f, fminf(x2, ss2[base0 + qq])
                                    - fmaxf(x1, ss1[base0 + qq]));
            float uni   = w + ssw[base0 + qq] - inter;
            if (inter / fmaxf(uni, 1e-9f) > 0.5f) m |= (1ull << qq);
        }
        smask[base0 + r] = m;
    }
    __syncthreads();

    // ---- greedy: thread per group ----
    if (tid < CC) {
        int kk = hist[tid], bb0 = offs[tid];
        unsigned long long sup = 0ull;
        if (kk <= 64) {
            for (int a = 0; a < kk; ++a)
                if (!((sup >> a) & 1ull)) sup |= smask[bb0 + a];
        } else {
            // robust serial fallback (practically never taken): flags in smask
            for (int a = 0; a < kk; ++a) smask[bb0 + a] = 0ull;
            for (int a = 0; a < kk; ++a) {
                if (smask[bb0 + a]) continue;
                float X1 = ss1[bb0 + a], X2 = ss2[bb0 + a], W = ssw[bb0 + a];
                for (int qq = a + 1; qq < kk; ++qq) {
                    float inter = fmaxf(0.0f, fminf(X2, ss2[bb0 + qq])
                                            - fmaxf(X1, ss1[bb0 + qq]));
                    float uni   = W + ssw[bb0 + qq] - inter;
                    if (inter / fmaxf(uni, 1e-9f) > 0.5f) smask[bb0 + qq] = 1ull;
                }
            }
        }
        gsup[tid] = sup;
    }
    __syncthreads();

    // ---- output keep mask (rank + group still in registers) ----
    if (tid < NN) {
        bool suppressed = (k <= 64) ? (((gsup[g] >> r) & 1ull) != 0ull)
                                    : (smask[base0 + r] != 0ull);
        out[OFF_KEEP + (size_t)b * NN + tid] = suppressed ? 0.0f : 1.0f;
    }
}

// ---------------------------------------------------------------------------
// Inputs (metadata order):
//  0 boxes_t          (128,500,2)    f32
//  1 predicted_class  (6,128,500,80) f32
//  2 predicted_boxes  (6,128,500,2)  f32
//  3 noise            (128,500,2)    f32
//  4 fresh_noise      (128,500,2)    f32
//  5 alphas_cumprod   (1000,)        f32
//  6 t_now            scalar         i32
//  7 t_next           scalar         i32
// ---------------------------------------------------------------------------
extern "C" void kernel_launch(void* const* d_in, const int* in_sizes, int n_in,
                              void* d_out, int out_size)
{
    const float* boxes_t = (const float*)d_in[0];
    const float* pc      = (const float*)d_in[1];
    const float* pb      = (const float*)d_in[2];
    const float* noise   = (const float*)d_in[3];
    const float* fresh   = (const float*)d_in[4];
    const float* ac      = (const float*)d_in[5];
    const int*   t_now   = (const int*)d_in[6];
    const int*   t_next  = (const int*)d_in[7];
    float* out = (float*)d_out;

    fused_kernel<<<BB, 512>>>(boxes_t, pc, pb, noise, fresh, ac, t_now, t_next, out);
}

// round 16
// speedup vs baseline: 3.3298x; 1.1263x over previous
#include <cuda_runtime.h>
#include <math.h>

// Shapes (fixed by the problem)
#define BB 128
#define NN 500
#define CC 80
// Head index used = 5 (last of 6)

// d_out layout (float32, 320000 elems):
//   [0      : 128000) boxes_next (B,N,2)
//   [128000 : 192000) scores     (B,N)
//   [192000 : 256000) labels     (B,N) as float
//   [256000 : 320000) nms_keep   (B,N) as 0/1 float
#define OFF_SCORES 128000
#define OFF_LABELS 192000
#define OFF_KEEP   256000

// ---------------------------------------------------------------------------
// ONE fused kernel: one block of 1024 threads (32 warps, 50% occ) per batch.
// Score phase: 4 lanes/row, 256 rows per pass, 2 software-pipelined passes.
// Each pass issues own-batch DRAM loads for pass p+1 and batch-0 L2 loads for
// pass p before reducing -> deep LSU queue from 32 warps. S-phase reduction
// arithmetic is bit-identical to the 16.8us baseline.
// NMS tail: label-bucketed rank-sort + 64-bit suppression masks + bitmask
// greedy per group (serial O(k^2) fallback for k>64 — never in practice).
// ---------------------------------------------------------------------------
__global__ __launch_bounds__(1024)
void fused_kernel(const float* __restrict__ boxes_t,
                  const float* __restrict__ pc,
                  const float* __restrict__ pb,
                  const float* __restrict__ noise,
                  const float* __restrict__ fresh,
                  const float* __restrict__ ac,
                  const int*   __restrict__ t_now_p,
                  const int*   __restrict__ t_next_p,
                  float* __restrict__ out)
{
    const int b      = blockIdx.x;
    const int tid    = threadIdx.x;
    const int q      = tid & 3;   // quarter of a row
    const int slot_b = tid >> 2;  // row-slot 0..255 per pass

    __shared__ int      skeep[NN];            // batch-0 keep mask
    __shared__ unsigned sukey[NN];            // ~bits(score) per row
    __shared__ int      slabel[NN];           // argmax label per row
    __shared__ unsigned long long gkey[NN];   // keys in grouped (unsorted) order
    __shared__ float ss1[NN], ss2[NN], ssw[NN];  // coords in sorted order
    __shared__ unsigned long long smask[NN];  // per sorted slot: mask / flag
    __shared__ unsigned long long gsup[CC];
    __shared__ int hist[CC], offs[CC], cur[CC];

    if (tid < CC) hist[tid] = 0;

    // ---- early independent loads: box-update operands (consumed in stage) --
    float2 bt, bs, nz, fz;
    if (tid < NN) {
        const size_t idx = (size_t)b * NN + tid;
        bt = ((const float2*)boxes_t)[idx];
        bs = ((const float2*)(pb + (size_t)5 * BB * NN * 2))[idx];
        nz = ((const float2*)noise)[idx];
        fz = ((const float2*)fresh)[idx];
    }
    // DDIM scalar chain (dependent loads — issued early)
    const int   t_now      = *t_now_p;
    const int   t_next     = *t_next_p;
    const float alpha      = ac[t_now];
    const float alpha_next = ac[t_next];

    const float* pc5 = pc + (size_t)5 * BB * NN * CC;

    // ---- pipelined score phases (2 passes of 256 rows) ----
    float4 sA[5], sB[5], kv[5];

    // prologue: own-batch (S) loads for pass 0
    {
        int slot  = slot_b;
        int slotc = slot < NN ? slot : NN - 1;
        const float4* rp = (const float4*)(pc5 + ((size_t)b * NN + slotc) * CC);
        #pragma unroll
        for (int i = 0; i < 5; ++i) sA[i] = __ldg(rp + q + 4 * i);
    }

    #pragma unroll
    for (int p = 0; p < 2; ++p) {
        float4* curb = (p & 1) ? sB : sA;
        float4* nxtb = (p & 1) ? sA : sB;

        // issue S loads for pass p+1 (DRAM) first
        if (p < 1) {
            int slot  = (p + 1) * 256 + slot_b;
            int slotc = slot < NN ? slot : NN - 1;
            const float4* rp = (const float4*)(pc5 + ((size_t)b * NN + slotc) * CC);
            #pragma unroll
            for (int i = 0; i < 5; ++i) nxtb[i] = __ldg(rp + q + 4 * i);
        }
        // issue K loads for pass p (batch 0, L2-broadcast)
        {
            int slot  = p * 256 + slot_b;
            int slotc = slot < NN ? slot : NN - 1;
            const float4* rp = (const float4*)(pc5 + (size_t)slotc * CC);
            #pragma unroll
            for (int i = 0; i < 5; ++i) kv[i] = __ldg(rp + q + 4 * i);
        }

        const int slot = p * 256 + slot_b;

        // ---- reduce K: batch-0 keep = (max over all 80 logits) > 0 ----
        {
            float m = fmaxf(fmaxf(fmaxf(kv[0].x, kv[0].y), fmaxf(kv[0].z, kv[0].w)),
                      fmaxf(fmaxf(fmaxf(kv[1].x, kv[1].y), fmaxf(kv[1].z, kv[1].w)),
                      fmaxf(fmaxf(fmaxf(kv[2].x, kv[2].y), fmaxf(kv[2].z, kv[2].w)),
                      fmaxf(fmaxf(fmaxf(kv[3].x, kv[3].y), fmaxf(kv[3].z, kv[3].w)),
                      fmaxf(fmaxf(kv[4].x, kv[4].y), fmaxf(kv[4].z, kv[4].w))))));
            m = fmaxf(m, __shfl_xor_sync(0xffffffffu, m, 1));
            m = fmaxf(m, __shfl_xor_sync(0xffffffffu, m, 2));
            if (q == 0 && slot < NN) skeep[slot] = (m > 0.0f);
        }

        // ---- reduce S: softmax score + argmax label (bit-identical) --------
        {
            float4 a0 = curb[0], a1 = curb[1], a2 = curb[2], a3 = curb[3], a4 = curb[4];

            float lmax = fmaxf(fmaxf(fmaxf(a0.x, a0.y), fmaxf(a0.z, a0.w)),
                         fmaxf(fmaxf(fmaxf(a1.x, a1.y), fmaxf(a1.z, a1.w)),
                         fmaxf(fmaxf(fmaxf(a2.x, a2.y), fmaxf(a2.z, a2.w)),
                         fmaxf(fmaxf(fmaxf(a3.x, a3.y), fmaxf(a3.z, a3.w)),
                         fmaxf(fmaxf(a4.x, a4.y), fmaxf(a4.z, a4.w))))));

            // local argmax over first 79 (exclude col 79 = q==3 lane's a4.w).
            float v; int ai;
            const int c0 = 4 * q;
            v = a0.x; ai = c0;
#define ARGM(val, col) if ((val) > v) { v = (val); ai = (col); }
            ARGM(a0.y, c0 + 1) ARGM(a0.z, c0 + 2) ARGM(a0.w, c0 + 3)
            ARGM(a1.x, c0 + 16) ARGM(a1.y, c0 + 17) ARGM(a1.z, c0 + 18) ARGM(a1.w, c0 + 19)
            ARGM(a2.x, c0 + 32) ARGM(a2.y, c0 + 33) ARGM(a2.z, c0 + 34) ARGM(a2.w, c0 + 35)
            ARGM(a3.x, c0 + 48) ARGM(a3.y, c0 + 49) ARGM(a3.z, c0 + 50) ARGM(a3.w, c0 + 51)
            ARGM(a4.x, c0 + 64) ARGM(a4.y, c0 + 65) ARGM(a4.z, c0 + 66)
            if (q != 3) ARGM(a4.w, c0 + 67)
#undef ARGM

            float m = lmax;
            m = fmaxf(m, __shfl_xor_sync(0xffffffffu, m, 1));
            m = fmaxf(m, __shfl_xor_sync(0xffffffffu, m, 2));

            #pragma unroll
            for (int o = 1; o <= 2; o <<= 1) {
                float ov = __shfl_xor_sync(0xffffffffu, v, o);
                int   oi = __shfl_xor_sync(0xffffffffu, ai, o);
                if (ov > v || (ov == v && oi < ai)) { v = ov; ai = oi; }
            }

            float s = __expf(a0.x - m) + __expf(a0.y - m) + __expf(a0.z - m) + __expf(a0.w - m)
                    + __expf(a1.x - m) + __expf(a1.y - m) + __expf(a1.z - m) + __expf(a1.w - m)
                    + __expf(a2.x - m) + __expf(a2.y - m) + __expf(a2.z - m) + __expf(a2.w - m)
                    + __expf(a3.x - m) + __expf(a3.y - m) + __expf(a3.z - m) + __expf(a3.w - m)
                    + __expf(a4.x - m) + __expf(a4.y - m) + __expf(a4.z - m) + __expf(a4.w - m);
            s += __shfl_xor_sync(0xffffffffu, s, 1);
            s += __shfl_xor_sync(0xffffffffu, s, 2);

            if (q == 0 && slot < NN) {
                float sc = __expf(v - m) / s;
                out[OFF_SCORES + (size_t)b * NN + slot] = sc;
                out[OFF_LABELS + (size_t)b * NN + slot] = (float)ai;
                sukey[slot]  = ~__float_as_uint(sc);  // scores > 0: order-preserving
                slabel[slot] = ai;
            }
        }
    }

    // DDIM scalars (same fp32 op sequence as reference)
    const float sqrt_recip   = sqrtf(1.0f / alpha);
    const float sqrt_recipm1 = sqrtf(1.0f / alpha - 1.0f);
    const float sigma = sqrtf((1.0f - alpha / alpha_next) * (1.0f - alpha_next)
                              / (1.0f - alpha));
    const float ccoef = sqrtf(1.0f - alpha_next - sigma * sigma);
    const float sq_an = sqrtf(alpha_next);

    __syncthreads();   // skeep / sukey / slabel / hist=0 visible

    // ---- stage: box update + NMS staging ----------------------------------
    float x1 = 0.0f, x2 = 0.0f, w = 0.0f;
    unsigned long long key = 0ull;
    int g = 0;
    if (tid < NN) {
        const size_t idx = (size_t)b * NN + tid;
        const int kp = skeep[tid];
        float pn0 = (sqrt_recip * bt.x - bs.x) / sqrt_recipm1;
        float pn1 = (sqrt_recip * bt.y - bs.y) / sqrt_recipm1;
        float2 u;
        u.x = kp ? bs.x * sq_an + ccoef * pn0 + sigma * nz.x : fz.x;
        u.y = kp ? bs.y * sq_an + ccoef * pn1 + sigma * nz.y : fz.y;
        ((float2*)out)[idx] = u;

        w  = fmaxf(bs.y, 0.0001f);
        x1 = bs.x - w * 0.5f;
        x2 = bs.x + w * 0.5f;

        key = ((unsigned long long)sukey[tid] << 32) | (unsigned)tid; // asc == (score desc, idx asc)
        g   = slabel[tid];
        atomicAdd(&hist[g], 1);
    }
    __syncthreads();

    // ---- prefix sum over 80 label bins: parallel per-thread ----
    if (tid < CC) {
        int acc = 0;
        for (int l = 0; l < tid; ++l) acc += hist[l];
        offs[tid] = acc;
        cur[tid]  = acc;
    }
    __syncthreads();

    // ---- scatter keys into grouped order ----
    if (tid < NN) {
        int pos = atomicAdd(&cur[g], 1);
        gkey[pos] = key;
    }
    __syncthreads();

    // ---- rank via sequential scan; build sorted coord arrays from registers --
    int base0 = 0, k = 0, r = 0;
    if (tid < NN) {
        base0 = offs[g];
        k     = hist[g];
        for (int i = 0; i < k; ++i)
            r += (gkey[base0 + i] < key);
        ss1[base0 + r] = x1;
        ss2[base0 + r] = x2;
        ssw[base0 + r] = w;
    }
    __syncthreads();

    // ---- suppression masks (sequential-address LDS, no indirection) ----
    if (tid < NN && k <= 64) {
        unsigned long long m = 0ull;
        for (int qq = r + 1; qq < k; ++qq) {
            float inter = fmaxf(0.0f, fminf(x2, ss2[base0 + qq])
                                    - fmaxf(x1, ss1[base0 + qq]));
            float uni   = w + ssw[base0 + qq] - inter;
            if (inter / fmaxf(uni, 1e-9f) > 0.5f) m |= (1ull << qq);
        }
        smask[base0 + r] = m;
    }
    __syncthreads();

    // ---- greedy: thread per group ----
    if (tid < CC) {
        int kk = hist[tid], bb0 = offs[tid];
        unsigned long long sup = 0ull;
        if (kk <= 64) {
            for (int a = 0; a < kk; ++a)
                if (!((sup >> a) & 1ull)) sup |= smask[bb0 + a];
        } else {
            // robust serial fallback (practically never taken): flags in smask
            for (int a = 0; a < kk; ++a) smask[bb0 + a] = 0ull;
            for (int a = 0; a < kk; ++a) {
                if (smask[bb0 + a]) continue;
                float X1 = ss1[bb0 + a], X2 = ss2[bb0 + a], W = ssw[bb0 + a];
                for (int qq = a + 1; qq < kk; ++qq) {
                    float inter = fmaxf(0.0f, fminf(X2, ss2[bb0 + qq])
                                            - fmaxf(X1, ss1[bb0 + qq]));
                    float uni   = W + ssw[bb0 + qq] - inter;
                    if (inter / fmaxf(uni, 1e-9f) > 0.5f) smask[bb0 + qq] = 1ull;
                }
            }
        }
        gsup[tid] = sup;
    }
    __syncthreads();

    // ---- output keep mask (rank + group still in registers) ----
    if (tid < NN) {
        bool suppressed = (k <= 64) ? (((gsup[g] >> r) & 1ull) != 0ull)
                                    : (smask[base0 + r] != 0ull);
        out[OFF_KEEP + (size_t)b * NN + tid] = suppressed ? 0.0f : 1.0f;
    }
}

// ---------------------------------------------------------------------------
// Inputs (metadata order):
//  0 boxes_t          (128,500,2)    f32
//  1 predicted_class  (6,128,500,80) f32
//  2 predicted_boxes  (6,128,500,2)  f32
//  3 noise            (128,500,2)    f32
//  4 fresh_noise      (128,500,2)    f32
//  5 alphas_cumprod   (1000,)        f32
//  6 t_now            scalar         i32
//  7 t_next           scalar         i32
// ---------------------------------------------------------------------------
extern "C" void kernel_launch(void* const* d_in, const int* in_sizes, int n_in,
                              void* d_out, int out_size)
{
    const float* boxes_t = (const float*)d_in[0];
    const float* pc      = (const float*)d_in[1];
    const float* pb      = (const float*)d_in[2];
    const float* noise   = (const float*)d_in[3];
    const float* fresh   = (const float*)d_in[4];
    const float* ac      = (const float*)d_in[5];
    const int*   t_now   = (const int*)d_in[6];
    const int*   t_next  = (const int*)d_in[7];
    float* out = (float*)d_out;

    fused_kernel<<<BB, 1024>>>(boxes_t, pc, pb, noise, fresh, ac, t_now, t_next, out);
}